// round 15
// baseline (speedup 1.0000x reference)
#include <cuda_runtime.h>
#include <cuda_bf16.h>
#include <cooperative_groups.h>

namespace cg = cooperative_groups;

#define N_ST   512
#define N_OBSV 1024
#define BATCH  64
#define TMAXL  512
#define CLUSTER_N 4
#define THREADS 256

/* ---- device scratch (no allocs) ----
   g_Pk[r][...]: CTA r's P[rows 0..511][k in 128r..128r+128) as packed pairs:
   idx = ((j*4+ksub)*16 + kp)*64 + rowgrp*8 + rr
   row i = 64j + rowgrp*8 + rr, in-block kpair = ksub*16 + kp.              */
__device__ unsigned g_Pk[CLUSTER_N * 32768];
__device__ float g_logET[N_OBSV * N_ST];
__device__ float g_expET[N_OBSV * N_ST];
__device__ float g_logPi[N_ST];
__device__ float g_icolsum[N_ST];

/* ---------------- PTX helpers ---------------- */

__device__ __forceinline__ unsigned s2u(const void* p) {
    return (unsigned)__cvta_generic_to_shared(p);
}

#define FMA2(acc, a, w) \
    asm("fma.rn.f32x2 %0, %1, %2, %0;" : "+l"(acc) : "l"(a), "l"(w))

#define MBARRIER_INIT(mbar, count) \
    asm volatile("mbarrier.init.shared.b64 [%0], %1;" \
        :: "r"(mbar), "r"((unsigned)(count)) : "memory")

#define MBARRIER_ARRIVE_CLUSTER(local_mbar, target_rank) \
    asm volatile( \
        "{\n\t" \
        ".reg .b32 remAddr32;\n\t" \
        "mapa.shared::cluster.u32 remAddr32, %0, %1;\n\t" \
        "mbarrier.arrive.release.cluster.shared::cluster.b64 _, [remAddr32];\n\t" \
        "}" \
        :: "r"(local_mbar), "r"((unsigned)(target_rank)) : "memory")

#define MBARRIER_WAIT_PARITY(mbar, parity) do { \
    unsigned _m = (mbar), _p = (parity), _done; \
    asm volatile( \
        "{\n\t.reg .pred p;\n\t" \
        "mbarrier.try_wait.parity.acquire.cta.shared::cta.b64 p, [%1], %2;\n\t" \
        "selp.b32 %0, 1, 0, p;\n\t}" \
        : "=r"(_done) : "r"(_m), "r"(_p) : "memory"); \
    if (!_done) { \
        asm volatile( \
            "{\n\t.reg .pred P1;\n\t" \
            "WL_%=:\n\t" \
            "mbarrier.try_wait.parity.acquire.cta.shared::cta.b64 P1, [%0], %1, 0x989680;\n\t" \
            "@P1 bra.uni WD_%=;\n\t" \
            "bra.uni WL_%=;\n\t" \
            "WD_%=:\n\t}" \
            :: "r"(_m), "r"(_p) : "memory"); \
    } \
} while (0)

/* ---------------- prep kernels ---------------- */

__global__ void prep_logpi(const float* __restrict__ pi) {
    __shared__ float red[8];
    int tid = threadIdx.x;
    float s = 0.f;
    for (int k = tid; k < N_ST; k += 256) s += __expf(pi[k]);
    for (int o = 16; o; o >>= 1) s += __shfl_xor_sync(0xffffffffu, s, o);
    if ((tid & 31) == 0) red[tid >> 5] = s;
    __syncthreads();
    float tot = 0.f;
    #pragma unroll
    for (int w = 0; w < 8; w++) tot += red[w];
    float l = __logf(tot);
    for (int k = tid; k < N_ST; k += 256) g_logPi[k] = pi[k] - l;
}

__global__ void prep_colsum(const float* __restrict__ A) {
    __shared__ float part[8][32];
    int kx = threadIdx.x & 31, iy = threadIdx.x >> 5;
    int k = blockIdx.x * 32 + kx;
    float s = 0.f;
    for (int i = iy; i < N_ST; i += 8) s += __expf(A[i * N_ST + k]);
    part[iy][kx] = s;
    __syncthreads();
    if (iy == 0) {
        float t = 0.f;
        #pragma unroll
        for (int j = 0; j < 8; j++) t += part[j][kx];
        g_icolsum[k] = 1.0f / t;
    }
}

/* low16 = bf16(pe) (recovered exactly via <<16); high16 rounded at prep so the
   raw u32 reinterpreted as f32 is the nearest repr of po given fixed low bits */
__device__ __forceinline__ unsigned pack_pair(float pe, float po) {
    unsigned lo = (unsigned)__bfloat16_as_ushort(__float2bfloat16(pe));
    unsigned ob = __float_as_uint(po);
    unsigned hi = (ob - lo + 0x8000u) >> 16;
    return lo | (hi << 16);
}

__global__ void prep_pk(const float* __restrict__ A) {
    int i   = blockIdx.x;        /* global row */
    int kpg = threadIdx.x;       /* global k-pair 0..255 */
    float p0 = __expf(A[i * N_ST + 2 * kpg])     * g_icolsum[2 * kpg];
    float p1 = __expf(A[i * N_ST + 2 * kpg + 1]) * g_icolsum[2 * kpg + 1];
    int r = kpg >> 6;
    int kpb = kpg & 63;
    int ksub = kpb >> 4, kp = kpb & 15;
    int j = i >> 6, rowgrp = (i >> 3) & 7, rr = i & 7;
    g_Pk[r * 32768 + ((j * 4 + ksub) * 16 + kp) * 64 + rowgrp * 8 + rr] =
        pack_pair(p0, p1);
}

__global__ void prep_logE(const float* __restrict__ E) {
    __shared__ float red[8];
    int i = blockIdx.x;
    int tid = threadIdx.x;
    float s = 0.f;
    for (int o = tid; o < N_OBSV; o += 256) s += __expf(E[i * N_OBSV + o]);
    for (int o = 16; o; o >>= 1) s += __shfl_xor_sync(0xffffffffu, s, o);
    if ((tid & 31) == 0) red[tid >> 5] = s;
    __syncthreads();
    float tot = 0.f;
    #pragma unroll
    for (int w = 0; w < 8; w++) tot += red[w];
    float l = __logf(tot);
    for (int o = tid; o < N_OBSV; o += 256) {
        float lv = E[i * N_OBSV + o] - l;
        g_logET[o * N_ST + i] = lv;
        g_expET[o * N_ST + i] = __expf(lv);
    }
}

/* ---------------- main persistent clustered kernel ---------------- */

#define P_BYTES  131072
#define YB_OFF   P_BYTES                 /* [2 par][4 src][2 b][128] f32 = 8192 */
#define W_OFF    (YB_OFF + 8192)         /* [2 b][128] f32 = 1024              */
#define SP_OFF   (W_OFF + 1024)          /* [2 par][2 b][16] f32 = 256         */
#define XS_OFF   (SP_OFF + 256)          /* [2 b][512] int = 4096              */
#define BAR_OFF  (XS_OFF + 4096)         /* ybar0, ybar1, spbar0, spbar1       */
#define RED_OFF  (BAR_OFF + 32)
#define SMEM_TOTAL (RED_OFF + 64)

extern __shared__ unsigned char smem_raw[];

__global__ void __cluster_dims__(CLUSTER_N, 1, 1) __launch_bounds__(THREADS, 1)
hmm_main(const int* __restrict__ x, const int* __restrict__ Tarr,
         float* __restrict__ out)
{
    cg::cluster_group cluster = cg::this_cluster();
    const unsigned rank = cluster.block_rank();
    const unsigned grp  = blockIdx.x / CLUSTER_N;

    const uint4* Ps4 = (const uint4*)smem_raw;
    float* yb  = (float*)(smem_raw + YB_OFF);
    float* wsh = (float*)(smem_raw + W_OFF);
    float* sp  = (float*)(smem_raw + SP_OFF);
    int*   xs  = (int*)(smem_raw + XS_OFF);
    float* red = (float*)(smem_raw + RED_OFF);
    const unsigned ybar0  = s2u(smem_raw + BAR_OFF);
    const unsigned ybar1  = ybar0 + 8;
    const unsigned spbar0 = ybar0 + 16;
    const unsigned spbar1 = ybar0 + 24;

    const int tid  = threadIdx.x;
    const int lane = tid & 31;
    const int warp = tid >> 5;          /* 0..7 */
    const int b2   = tid >> 7;          /* batch in scalar phases */
    const int ri   = tid & 127;         /* row-in-chunk in scalar phases */
    const int ksub = lane >> 3;         /* dot: k-subslice 0..3 */
    const int rowgrp = lane & 7;        /* dot: row group 0..7 (unused directly) */
    const int chunk = warp >> 1;        /* dot: dst rank for this warp's rows */
    (void)rowgrp;

    if (tid == 0) {
        MBARRIER_INIT(ybar0, 64);  MBARRIER_INIT(ybar1, 64);
        MBARRIER_INIT(spbar0, 32); MBARRIER_INIT(spbar1, 32);
    }

    /* load P block (coalesced 16B) */
    {
        const uint4* Pg = (const uint4*)(g_Pk + rank * 32768);
        uint4* Pd = (uint4*)smem_raw;
        for (int s = tid; s < 8192; s += THREADS) Pd[s] = Pg[s];
    }
    for (int s = tid; s < 2 * TMAXL; s += THREADS)
        xs[s] = x[grp * 2 * TMAXL + s];

    const int T0v = Tarr[grp * 2 + 0];
    const int T1v = Tarr[grp * 2 + 1];
    const int Tmax = max(T0v, T1v);

    /* ---- init: w_0 chunk, C = m, push S_0 partials to sp[1] ---- */
    float C0, C1;
    {
        __syncthreads();   /* xs + P visible */
        int x0 = xs[b2 * TMAXL];
        float a0, a1, a2, a3;
        {
            int s0 = ri, s1 = ri + 128, s2 = ri + 256, s3 = ri + 384;
            a0 = g_logPi[s0] + g_logET[x0 * N_ST + s0];
            a1 = g_logPi[s1] + g_logET[x0 * N_ST + s1];
            a2 = g_logPi[s2] + g_logET[x0 * N_ST + s2];
            a3 = g_logPi[s3] + g_logET[x0 * N_ST + s3];
        }
        float lm = fmaxf(fmaxf(a0, a1), fmaxf(a2, a3));
        #pragma unroll
        for (int o = 16; o; o >>= 1) lm = fmaxf(lm, __shfl_xor_sync(0xffffffffu, lm, o));
        if (lane == 0) red[warp] = lm;
        __syncthreads();
        const float m0 = fmaxf(fmaxf(red[0], red[1]), fmaxf(red[2], red[3]));
        const float m1 = fmaxf(fmaxf(red[4], red[5]), fmaxf(red[6], red[7]));
        C0 = m0; C1 = m1;
        const float m = b2 ? m1 : m0;
        float e0 = __expf(a0 - m), e1 = __expf(a1 - m);
        float e2 = __expf(a2 - m), e3 = __expf(a3 - m);
        /* own chunk value: state = 128*rank + ri */
        float wv = (rank == 0) ? e0 : (rank == 1) ? e1 : (rank == 2) ? e2 : e3;
        wsh[b2 * 128 + ri] = wv;
        /* S_0 chunk partials -> sp[1] on all ranks (visible after cluster.sync) */
        float psum = wv;
        #pragma unroll
        for (int o = 16; o; o >>= 1) psum += __shfl_xor_sync(0xffffffffu, psum, o);
        if (lane == 0) {
            float* slot = sp + 1 * 32 + b2 * 16 + (int)rank * 4 + (warp & 3);
            #pragma unroll
            for (int dr = 0; dr < CLUSTER_N; ++dr)
                *cluster.map_shared_rank(slot, dr) = psum;
        }
        __syncthreads();   /* wsh visible */
    }
    cluster.sync();   /* barriers + w_0 + sp[1] ready everywhere */

    unsigned ph0 = 0, ph1 = 0, sph0 = 0, sph1 = 0;

    /* ===== loop: tau = 0..Tmax-1. Iter tau: (tau>=1: consume y_{tau-1},
       S_{tau-1}; form w_tau; push S_tau partials) then dot y_tau & push. ===== */
    for (int tau = 0; tau < Tmax; ++tau) {
        const int parp = (tau + 1) & 1;

        if (tau > 0) {
            const int parc = tau & 1;
            /* em prefetch (long-latency LDG overlaps the waits) */
            const int xv = xs[b2 * TMAXL + tau];
            const float em = g_expET[xv * N_ST + 128 * (int)rank + ri];

            if (parc) { MBARRIER_WAIT_PARITY(ybar1, ph1); ph1 ^= 1; }
            else      { MBARRIER_WAIT_PARITY(ybar0, ph0); ph0 ^= 1; }
            if (tau >= 2) {
                if (parc) { MBARRIER_WAIT_PARITY(spbar1, sph1); sph1 ^= 1; }
                else      { MBARRIER_WAIT_PARITY(spbar0, sph0); sph0 ^= 1; }
            }

            /* S_{tau-1} from 16 partials per batch */
            const float* spc = sp + parc * 32;
            float4 qa = *(const float4*)(spc + 0),  qb = *(const float4*)(spc + 4);
            float4 qc = *(const float4*)(spc + 8),  qd = *(const float4*)(spc + 12);
            float4 ra = *(const float4*)(spc + 16), rb = *(const float4*)(spc + 20);
            float4 rc = *(const float4*)(spc + 24), rd = *(const float4*)(spc + 28);
            const float S0 = ((qa.x + qa.y) + (qa.z + qa.w)) + ((qb.x + qb.y) + (qb.z + qb.w))
                           + ((qc.x + qc.y) + (qc.z + qc.w)) + ((qd.x + qd.y) + (qd.z + qd.w));
            const float S1 = ((ra.x + ra.y) + (ra.z + ra.w)) + ((rb.x + rb.y) + (rb.z + rb.w))
                           + ((rc.x + rc.y) + (rc.z + rc.w)) + ((rd.x + rd.y) + (rd.z + rd.w));
            C0 += __logf(S0);
            C1 += __logf(S1);
            if (rank == 0 && tid == 0) {
                if (T0v == tau) out[grp * 2 + 0] = C0;
                if (T1v == tau) out[grp * 2 + 1] = C1;
            }
            const float invSp = __frcp_rn(b2 ? S1 : S0);

            /* form w_tau (own chunk) */
            const float* ybc = yb + (parc * 4) * 256 + b2 * 128 + ri;
            const float d = (ybc[0] + ybc[256]) + (ybc[512] + ybc[768]);
            const float wv = em * d * invSp;
            wsh[b2 * 128 + ri] = wv;

            /* S_tau partials -> sp[parp] on all ranks, covered by spbar */
            float psum = wv;
            #pragma unroll
            for (int o = 16; o; o >>= 1) psum += __shfl_xor_sync(0xffffffffu, psum, o);
            if (lane == 0) {
                float* slot = sp + parp * 32 + b2 * 16 + (int)rank * 4 + (warp & 3);
                #pragma unroll
                for (int dr = 0; dr < CLUSTER_N; ++dr)
                    *cluster.map_shared_rank(slot, dr) = psum;
                #pragma unroll
                for (int dr = 0; dr < CLUSTER_N; ++dr) {
                    if (parp) MBARRIER_ARRIVE_CLUSTER(spbar1, dr);
                    else      MBARRIER_ARRIVE_CLUSTER(spbar0, dr);
                }
            }
            __syncthreads();   /* w_tau visible to all warps */
        }

        /* ---- dot: y_tau = P[:, own k-block] . w_tau[own chunk] ----
           warp j: rows 64j..64j+63; lane = ksub*8+rowgrp;
           thread: 8 rows x 32 k x 2 batches.                          */
        {
            const uint4* Pp = Ps4 + ((warp * 4 + ksub) * 16) * 16 + (lane & 7) * 2;
            const unsigned long long* W0 =
                (const unsigned long long*)(wsh + ksub * 32);
            const unsigned long long* W1 =
                (const unsigned long long*)(wsh + 128 + ksub * 32);

            unsigned long long accA[8], accB[8];
            #pragma unroll
            for (int r8 = 0; r8 < 8; ++r8) { accA[r8] = 0ull; accB[r8] = 0ull; }

            #pragma unroll
            for (int kp = 0; kp < 16; ++kp) {
                uint4 qa = Pp[kp * 16];
                uint4 qb = Pp[kp * 16 + 1];
                unsigned long long w0 = W0[kp];
                unsigned long long w1 = W1[kp];
                unsigned long long a;
                a = ((unsigned long long)qa.x << 32) | (unsigned)(qa.x << 16);
                FMA2(accA[0], a, w0);  FMA2(accB[0], a, w1);
                a = ((unsigned long long)qa.y << 32) | (unsigned)(qa.y << 16);
                FMA2(accA[1], a, w0);  FMA2(accB[1], a, w1);
                a = ((unsigned long long)qa.z << 32) | (unsigned)(qa.z << 16);
                FMA2(accA[2], a, w0);  FMA2(accB[2], a, w1);
                a = ((unsigned long long)qa.w << 32) | (unsigned)(qa.w << 16);
                FMA2(accA[3], a, w0);  FMA2(accB[3], a, w1);
                a = ((unsigned long long)qb.x << 32) | (unsigned)(qb.x << 16);
                FMA2(accA[4], a, w0);  FMA2(accB[4], a, w1);
                a = ((unsigned long long)qb.y << 32) | (unsigned)(qb.y << 16);
                FMA2(accA[5], a, w0);  FMA2(accB[5], a, w1);
                a = ((unsigned long long)qb.z << 32) | (unsigned)(qb.z << 16);
                FMA2(accA[6], a, w0);  FMA2(accB[6], a, w1);
                a = ((unsigned long long)qb.w << 32) | (unsigned)(qb.w << 16);
                FMA2(accA[7], a, w0);  FMA2(accB[7], a, w1);
            }

            float dA[8], dB[8];
            #pragma unroll
            for (int r8 = 0; r8 < 8; ++r8) {
                dA[r8] = __uint_as_float((unsigned)accA[r8])
                       + __uint_as_float((unsigned)(accA[r8] >> 32));
                dB[r8] = __uint_as_float((unsigned)accB[r8])
                       + __uint_as_float((unsigned)(accB[r8] >> 32));
            }
            /* combine across 4 ksub lanes (lane bits 3,4) */
            #pragma unroll
            for (int r8 = 0; r8 < 8; ++r8) {
                dA[r8] += __shfl_xor_sync(0xffffffffu, dA[r8], 8);
                dA[r8] += __shfl_xor_sync(0xffffffffu, dA[r8], 16);
                dB[r8] += __shfl_xor_sync(0xffffffffu, dB[r8], 8);
                dB[r8] += __shfl_xor_sync(0xffffffffu, dB[r8], 16);
            }

            /* push: lanes 0..7 carry rows (64*warp + lane*8 + 0..7);
               each pushing lane release-arrives after its own stores  */
            if (lane < 8) {
                const int rib = (warp & 1) * 64 + lane * 8;
                float* dst0 = yb + (parp * 4 + (int)rank) * 256 + 0 * 128 + rib;
                float* dst1 = yb + (parp * 4 + (int)rank) * 256 + 1 * 128 + rib;
                float4 vA0 = make_float4(dA[0], dA[1], dA[2], dA[3]);
                float4 vA1 = make_float4(dA[4], dA[5], dA[6], dA[7]);
                float4 vB0 = make_float4(dB[0], dB[1], dB[2], dB[3]);
                float4 vB1 = make_float4(dB[4], dB[5], dB[6], dB[7]);
                *(float4*)cluster.map_shared_rank(dst0,     chunk) = vA0;
                *(float4*)cluster.map_shared_rank(dst0 + 4, chunk) = vA1;
                *(float4*)cluster.map_shared_rank(dst1,     chunk) = vB0;
                *(float4*)cluster.map_shared_rank(dst1 + 4, chunk) = vB1;
                if (parp) MBARRIER_ARRIVE_CLUSTER(ybar1, chunk);
                else      MBARRIER_ARRIVE_CLUSTER(ybar0, chunk);
            }
        }
    }

    /* ---- epilogue: consume S_{Tmax-1}, write T==Tmax; drain y pushes ---- */
    {
        const int parc = Tmax & 1;
        if (parc) { MBARRIER_WAIT_PARITY(ybar1, ph1); }
        else      { MBARRIER_WAIT_PARITY(ybar0, ph0); }
        if (Tmax >= 2) {
            if (parc) { MBARRIER_WAIT_PARITY(spbar1, sph1); }
            else      { MBARRIER_WAIT_PARITY(spbar0, sph0); }
        }
        if (rank == 0 && tid == 0) {
            const float* spc = sp + parc * 32;
            float S0 = 0.f, S1 = 0.f;
            #pragma unroll
            for (int q = 0; q < 16; ++q) { S0 += spc[q]; S1 += spc[16 + q]; }
            C0 += __logf(S0);
            C1 += __logf(S1);
            if (T0v == Tmax) out[grp * 2 + 0] = C0;
            if (T1v == Tmax) out[grp * 2 + 1] = C1;
        }
    }
}

/* ---------------- launch ---------------- */

extern "C" void kernel_launch(void* const* d_in, const int* in_sizes, int n_in,
                              void* d_out, int out_size)
{
    const float* pi = (const float*)d_in[0];
    const float* A  = (const float*)d_in[1];
    const float* E  = (const float*)d_in[2];
    const int*   x  = (const int*)d_in[3];
    const int*   T  = (const int*)d_in[4];
    float* out = (float*)d_out;

    cudaFuncSetAttribute(hmm_main, cudaFuncAttributeMaxDynamicSharedMemorySize, SMEM_TOTAL);

    prep_logpi<<<1, 256>>>(pi);
    prep_colsum<<<16, 256>>>(A);
    prep_pk<<<N_ST, 256>>>(A);
    prep_logE<<<N_ST, 256>>>(E);
    hmm_main<<<(BATCH / 2) * CLUSTER_N, THREADS, SMEM_TOTAL>>>(x, T, out);
}

// round 16
// speedup vs baseline: 1.3746x; 1.3746x over previous
#include <cuda_runtime.h>
#include <cuda_bf16.h>
#include <cooperative_groups.h>

namespace cg = cooperative_groups;

#define N_ST   512
#define N_OBSV 1024
#define BATCH  64
#define TMAXL  512
#define CLUSTER_N 4
#define THREADS 256

/* ---- device scratch (no allocs) ----
   g_P4[kp*128 + rank*32 + rg] : uint4 = rows (4rg..4rg+3) of CTA 'rank',
   each u32 = compensation-packed pair (P[r][2kp], P[r][2kp+1])            */
__device__ uint4 g_P4[256 * 128];
__device__ float g_logET[N_OBSV * N_ST]; /* [obs][state] log emission  */
__device__ float g_expET[N_OBSV * N_ST]; /* [obs][state] emission prob */
__device__ float g_logPi[N_ST];
__device__ float g_icolsum[N_ST];

/* ---------------- PTX helpers ---------------- */

__device__ __forceinline__ unsigned s2u(const void* p) {
    return (unsigned)__cvta_generic_to_shared(p);
}

#define FMA2(acc, a, w) \
    asm("fma.rn.f32x2 %0, %1, %2, %0;" : "+l"(acc) : "l"(a), "l"(w))

#define MBARRIER_INIT(mbar, count) \
    asm volatile("mbarrier.init.shared.b64 [%0], %1;" \
        :: "r"(mbar), "r"((unsigned)(count)) : "memory")

#define MBARRIER_ARRIVE_CLUSTER(local_mbar, target_rank) \
    asm volatile( \
        "{\n\t" \
        ".reg .b32 remAddr32;\n\t" \
        "mapa.shared::cluster.u32 remAddr32, %0, %1;\n\t" \
        "mbarrier.arrive.release.cluster.shared::cluster.b64 _, [remAddr32];\n\t" \
        "}" \
        :: "r"(local_mbar), "r"((unsigned)(target_rank)) : "memory")

#define MBARRIER_WAIT_PARITY(mbar, parity) do { \
    unsigned _m = (mbar), _p = (parity), _done; \
    asm volatile( \
        "{\n\t.reg .pred p;\n\t" \
        "mbarrier.try_wait.parity.acquire.cta.shared::cta.b64 p, [%1], %2;\n\t" \
        "selp.b32 %0, 1, 0, p;\n\t}" \
        : "=r"(_done) : "r"(_m), "r"(_p) : "memory"); \
    if (!_done) { \
        asm volatile( \
            "{\n\t.reg .pred P1;\n\t" \
            "WL_%=:\n\t" \
            "mbarrier.try_wait.parity.acquire.cta.shared::cta.b64 P1, [%0], %1, 0x989680;\n\t" \
            "@P1 bra.uni WD_%=;\n\t" \
            "bra.uni WL_%=;\n\t" \
            "WD_%=:\n\t}" \
            :: "r"(_m), "r"(_p) : "memory"); \
    } \
} while (0)

/* ---------------- prep kernels ---------------- */

__global__ void prep_logpi(const float* __restrict__ pi) {
    __shared__ float red[8];
    int tid = threadIdx.x;
    float s = 0.f;
    for (int k = tid; k < N_ST; k += 256) s += __expf(pi[k]);
    for (int o = 16; o; o >>= 1) s += __shfl_xor_sync(0xffffffffu, s, o);
    if ((tid & 31) == 0) red[tid >> 5] = s;
    __syncthreads();
    float tot = 0.f;
    #pragma unroll
    for (int w = 0; w < 8; w++) tot += red[w];
    float l = __logf(tot);
    for (int k = tid; k < N_ST; k += 256) g_logPi[k] = pi[k] - l;
}

__global__ void prep_colsum(const float* __restrict__ A) {
    __shared__ float part[8][32];
    int kx = threadIdx.x & 31, iy = threadIdx.x >> 5;
    int k = blockIdx.x * 32 + kx;
    float s = 0.f;
    for (int i = iy; i < N_ST; i += 8) s += __expf(A[i * N_ST + k]);
    part[iy][kx] = s;
    __syncthreads();
    if (iy == 0) {
        float t = 0.f;
        #pragma unroll
        for (int j = 0; j < 8; j++) t += part[j][kx];
        g_icolsum[k] = 1.0f / t;
    }
}

/* low16 = bf16(pe) (recovered exactly via <<16); high16 rounded at prep so the
   raw u32 reinterpreted as f32 is the nearest repr of po given fixed low bits */
__device__ __forceinline__ unsigned pack_pair(float pe, float po) {
    unsigned lo = (unsigned)__bfloat16_as_ushort(__float2bfloat16(pe));
    unsigned ob = __float_as_uint(po);
    unsigned hi = (ob - lo + 0x8000u) >> 16;
    return lo | (hi << 16);
}

__global__ void prep_pt(const float* __restrict__ A) {
    int i  = blockIdx.x;        /* row  */
    int kp = threadIdx.x;       /* 0..255 k-pair */
    float p0 = __expf(A[i * N_ST + 2 * kp])     * g_icolsum[2 * kp];
    float p1 = __expf(A[i * N_ST + 2 * kp + 1]) * g_icolsum[2 * kp + 1];
    int rank = i >> 7, rg = (i >> 2) & 31, j = i & 3;
    ((unsigned*)g_P4)[((kp * 128) + rank * 32 + rg) * 4 + j] = pack_pair(p0, p1);
}

__global__ void prep_logE(const float* __restrict__ E) {
    __shared__ float red[8];
    int i = blockIdx.x;
    int tid = threadIdx.x;
    float s = 0.f;
    for (int o = tid; o < N_OBSV; o += 256) s += __expf(E[i * N_OBSV + o]);
    for (int o = 16; o; o >>= 1) s += __shfl_xor_sync(0xffffffffu, s, o);
    if ((tid & 31) == 0) red[tid >> 5] = s;
    __syncthreads();
    float tot = 0.f;
    #pragma unroll
    for (int w = 0; w < 8; w++) tot += red[w];
    float l = __logf(tot);
    for (int o = tid; o < N_OBSV; o += 256) {
        float lv = E[i * N_OBSV + o] - l;
        g_logET[o * N_ST + i] = lv;
        g_expET[o * N_ST + i] = __expf(lv);
    }
}

/* ---------------- main persistent clustered kernel ---------------- */

#define U_STRIDE 544                               /* 512 u + 32 partials */
#define P_BYTES  131072
#define U_OFF    P_BYTES
#define XS_OFF   (U_OFF + 4 * U_STRIDE * 4)        /* 139776 */
#define BAR_OFF  (XS_OFF + 2 * TMAXL * 4)          /* 143872 */
#define RED_OFF  (BAR_OFF + 16)
#define SMEM_TOTAL (RED_OFF + 64)

extern __shared__ unsigned char smem_raw[];

__global__ void __cluster_dims__(CLUSTER_N, 1, 1) __launch_bounds__(THREADS, 1)
hmm_main(const int* __restrict__ x, const int* __restrict__ Tarr,
         float* __restrict__ out)
{
    cg::cluster_group cluster = cg::this_cluster();
    const unsigned rank = cluster.block_rank();
    const unsigned grp  = blockIdx.x / CLUSTER_N;

    const uint4* Ps4 = (const uint4*)smem_raw;      /* [kp*32 + rg]            */
    float* uarr = (float*)(smem_raw + U_OFF);       /* [(buf*2+b)*U_STRIDE+.]  */
    int*   xs   = (int*)(smem_raw + XS_OFF);        /* [2][512]                */
    float* red  = (float*)(smem_raw + RED_OFF);
    const unsigned bar0 = s2u(smem_raw + BAR_OFF);
    const unsigned bar1 = bar0 + 8;

    const int tid  = threadIdx.x;
    const int lane = tid & 31;
    const int warp = tid >> 5;        /* dot: 16-row group */
    const int ksub = lane >> 2;       /* dot: k-subslice 0..7 */
    const int rq   = lane & 3;        /* dot: 4-row subgroup 0..3 */
    const int b2   = tid >> 7;        /* init: batch */
    const int il   = tid & 127;       /* init: row */

    if (tid == 0) { MBARRIER_INIT(bar0, CLUSTER_N); MBARRIER_INIT(bar1, CLUSTER_N); }

    /* load P slice (coalesced 16B) */
    {
        uint4* Pd = (uint4*)smem_raw;
        for (int s = tid; s < 8192; s += THREADS) {
            int kp = s >> 5, rg = s & 31;
            Pd[s] = g_P4[kp * 128 + rank * 32 + rg];
        }
    }
    for (int s = tid; s < 2 * TMAXL; s += THREADS)
        xs[s] = x[grp * 2 * TMAXL + s];

    const int T0v = Tarr[grp * 2 + 0];
    const int T1v = Tarr[grp * 2 + 1];
    const int Tc  = max(T0v, T1v);

    /* ---- init: u_0 = exp(alpha0 - m), full & replicated per CTA ---- */
    float C0, C1;
    {
        __syncthreads();   /* xs + P visible */
        int x0 = xs[b2 * TMAXL];
        float a0i[4];
        float lm = -3.402823466e38f;
        #pragma unroll
        for (int j = 0; j < 4; j++) {
            int s = il + 128 * j;
            a0i[j] = g_logPi[s] + g_logET[x0 * N_ST + s];
            lm = fmaxf(lm, a0i[j]);
        }
        #pragma unroll
        for (int o = 16; o; o >>= 1) lm = fmaxf(lm, __shfl_xor_sync(0xffffffffu, lm, o));
        if (lane == 0) red[warp] = lm;
        __syncthreads();
        const float m0 = fmaxf(fmaxf(red[0], red[1]), fmaxf(red[2], red[3]));
        const float m1 = fmaxf(fmaxf(red[4], red[5]), fmaxf(red[6], red[7]));
        C0 = m0; C1 = m1;
        const float m = b2 ? m1 : m0;
        float* u0b = uarr + b2 * U_STRIDE;
        float ls = 0.f;
        #pragma unroll
        for (int j = 0; j < 4; j++) {
            int s = il + 128 * j;
            float uv = __expf(a0i[j] - m);
            u0b[s] = uv;
            ls += uv;
        }
        #pragma unroll
        for (int o = 16; o; o >>= 1) ls += __shfl_xor_sync(0xffffffffu, ls, o);
        if (lane == 0) u0b[512 + (warp & 3)] = ls;     /* 4 partials   */
        if (il >= 4 && il < 32) u0b[512 + il] = 0.f;   /* zero 4..31   */
        __syncthreads();
    }
    cluster.sync();   /* barrier init + u0 ready everywhere */

    unsigned ph0 = 0, ph1 = 0;

    for (int t = 0; t < Tc; ++t) {
        if (t > 0) {
            if ((t - 1) & 1) { MBARRIER_WAIT_PARITY(bar1, ph1); ph1 ^= 1; }
            else             { MBARRIER_WAIT_PARITY(bar0, ph0); ph0 ^= 1; }
        }

        const int buf = t & 1;
        float* ub0 = uarr + (buf * 2 + 0) * U_STRIDE;
        float* ub1 = ub0 + U_STRIDE;
        const bool last = (t == Tc - 1);

        float dA[4], dB[4];
        float4 em0, em1;
        const int rowb = warp * 16 + rq * 4;      /* local row base (lanes<4) */

        if (!last) {
            /* em prefetch (lanes 0-3 carry rows; both batches) */
            const int xv0 = xs[t + 1];
            const int xv1 = xs[TMAXL + t + 1];
            if (lane < 4) {
                em0 = *(const float4*)&g_expET[xv0 * N_ST + 128 * (int)rank + rowb];
                em1 = *(const float4*)&g_expET[xv1 * N_ST + 128 * (int)rank + rowb];
            }

            /* ---- dot: warp = 16 rows (all k), lane = (ksub, rq) ----
               thread: 4 rows x 32 k x 2 batches; in-warp k-combine.    */
            const uint4* Pp = Ps4 + (warp * 4 + rq);        /* + kp*32 */
            const ulonglong2* W0 = (const ulonglong2*)ub0;
            const ulonglong2* W1 = (const ulonglong2*)ub1;

            unsigned long long accA0 = 0, accA1 = 0, accA2 = 0, accA3 = 0;
            unsigned long long accB0 = 0, accB1 = 0, accB2 = 0, accB3 = 0;

            #pragma unroll
            for (int j2 = 0; j2 < 16; ++j2) {
                const int wj = ksub * 16 + ((j2 + ksub) & 15);  /* bank-rotated */
                ulonglong2 w0 = W0[wj];
                ulonglong2 w1 = W1[wj];
                uint4 qa = Pp[(2 * wj) * 32];
                uint4 qb = Pp[(2 * wj + 1) * 32];

                unsigned long long a0, a1, a2, a3;
                a0 = ((unsigned long long)qa.x << 32) | (unsigned)(qa.x << 16);
                a1 = ((unsigned long long)qa.y << 32) | (unsigned)(qa.y << 16);
                a2 = ((unsigned long long)qa.z << 32) | (unsigned)(qa.z << 16);
                a3 = ((unsigned long long)qa.w << 32) | (unsigned)(qa.w << 16);
                FMA2(accA0, a0, w0.x);  FMA2(accB0, a0, w1.x);
                FMA2(accA1, a1, w0.x);  FMA2(accB1, a1, w1.x);
                FMA2(accA2, a2, w0.x);  FMA2(accB2, a2, w1.x);
                FMA2(accA3, a3, w0.x);  FMA2(accB3, a3, w1.x);

                a0 = ((unsigned long long)qb.x << 32) | (unsigned)(qb.x << 16);
                a1 = ((unsigned long long)qb.y << 32) | (unsigned)(qb.y << 16);
                a2 = ((unsigned long long)qb.z << 32) | (unsigned)(qb.z << 16);
                a3 = ((unsigned long long)qb.w << 32) | (unsigned)(qb.w << 16);
                FMA2(accA0, a0, w0.y);  FMA2(accB0, a0, w1.y);
                FMA2(accA1, a1, w0.y);  FMA2(accB1, a1, w1.y);
                FMA2(accA2, a2, w0.y);  FMA2(accB2, a2, w1.y);
                FMA2(accA3, a3, w0.y);  FMA2(accB3, a3, w1.y);
            }

            dA[0] = __uint_as_float((unsigned)accA0) + __uint_as_float((unsigned)(accA0 >> 32));
            dA[1] = __uint_as_float((unsigned)accA1) + __uint_as_float((unsigned)(accA1 >> 32));
            dA[2] = __uint_as_float((unsigned)accA2) + __uint_as_float((unsigned)(accA2 >> 32));
            dA[3] = __uint_as_float((unsigned)accA3) + __uint_as_float((unsigned)(accA3 >> 32));
            dB[0] = __uint_as_float((unsigned)accB0) + __uint_as_float((unsigned)(accB0 >> 32));
            dB[1] = __uint_as_float((unsigned)accB1) + __uint_as_float((unsigned)(accB1 >> 32));
            dB[2] = __uint_as_float((unsigned)accB2) + __uint_as_float((unsigned)(accB2 >> 32));
            dB[3] = __uint_as_float((unsigned)accB3) + __uint_as_float((unsigned)(accB3 >> 32));
            /* in-warp k-combine across ksub (lane bits 2,3,4) */
            #pragma unroll
            for (int r = 0; r < 4; ++r) {
                dA[r] += __shfl_xor_sync(0xffffffffu, dA[r], 4);
                dA[r] += __shfl_xor_sync(0xffffffffu, dA[r], 8);
                dA[r] += __shfl_xor_sync(0xffffffffu, dA[r], 16);
                dB[r] += __shfl_xor_sync(0xffffffffu, dB[r], 4);
                dB[r] += __shfl_xor_sync(0xffffffffu, dB[r], 8);
                dB[r] += __shfl_xor_sync(0xffffffffu, dB[r], 16);
            }
        }

        /* ---- S block (off the post-wait critical path) ---- */
        float4 p0a = *(const float4*)(ub0 + 512), p0b = *(const float4*)(ub0 + 516);
        float4 p0c = *(const float4*)(ub0 + 520), p0d = *(const float4*)(ub0 + 524);
        float4 p0e = *(const float4*)(ub0 + 528), p0f = *(const float4*)(ub0 + 532);
        float4 p0g = *(const float4*)(ub0 + 536), p0h = *(const float4*)(ub0 + 540);
        float4 p1a = *(const float4*)(ub1 + 512), p1b = *(const float4*)(ub1 + 516);
        float4 p1c = *(const float4*)(ub1 + 520), p1d = *(const float4*)(ub1 + 524);
        float4 p1e = *(const float4*)(ub1 + 528), p1f = *(const float4*)(ub1 + 532);
        float4 p1g = *(const float4*)(ub1 + 536), p1h = *(const float4*)(ub1 + 540);
        const float S0 =
            ((((p0a.x + p0a.y) + (p0a.z + p0a.w)) + ((p0b.x + p0b.y) + (p0b.z + p0b.w)))
           + (((p0c.x + p0c.y) + (p0c.z + p0c.w)) + ((p0d.x + p0d.y) + (p0d.z + p0d.w))))
          + ((((p0e.x + p0e.y) + (p0e.z + p0e.w)) + ((p0f.x + p0f.y) + (p0f.z + p0f.w)))
           + (((p0g.x + p0g.y) + (p0g.z + p0g.w)) + ((p0h.x + p0h.y) + (p0h.z + p0h.w))));
        const float S1 =
            ((((p1a.x + p1a.y) + (p1a.z + p1a.w)) + ((p1b.x + p1b.y) + (p1b.z + p1b.w)))
           + (((p1c.x + p1c.y) + (p1c.z + p1c.w)) + ((p1d.x + p1d.y) + (p1d.z + p1d.w))))
          + ((((p1e.x + p1e.y) + (p1e.z + p1e.w)) + ((p1f.x + p1f.y) + (p1f.z + p1f.w)))
           + (((p1g.x + p1g.y) + (p1g.z + p1g.w)) + ((p1h.x + p1h.y) + (p1h.z + p1h.w))));
        C0 += __logf(S0);
        C1 += __logf(S1);

        if (rank == 0 && tid == 0) {
            if (t == T0v - 1) out[grp * 2 + 0] = C0;
            if (t == T1v - 1) out[grp * 2 + 1] = C1;
        }
        if (last) break;

        const float invS0 = __frcp_rn(S0);
        const float invS1 = __frcp_rn(S1);

        /* ---- phase 2: lanes 0-3 finalize 4 rows x 2 batches, push ---- */
        float pA = 0.f, pB = 0.f;
        float4 vA, vB;
        if (lane < 4) {
            vA.x = em0.x * dA[0] * invS0;  vA.y = em0.y * dA[1] * invS0;
            vA.z = em0.z * dA[2] * invS0;  vA.w = em0.w * dA[3] * invS0;
            vB.x = em1.x * dB[0] * invS1;  vB.y = em1.y * dB[1] * invS1;
            vB.z = em1.z * dB[2] * invS1;  vB.w = em1.w * dB[3] * invS1;
            pA = (vA.x + vA.y) + (vA.z + vA.w);
            pB = (vB.x + vB.y) + (vB.z + vB.w);
        }
        pA += __shfl_xor_sync(0xffffffffu, pA, 1);
        pA += __shfl_xor_sync(0xffffffffu, pA, 2);
        pB += __shfl_xor_sync(0xffffffffu, pB, 1);
        pB += __shfl_xor_sync(0xffffffffu, pB, 2);

        const int nb = buf ^ 1;
        float* db0 = uarr + (nb * 2 + 0) * U_STRIDE;
        float* db1 = db0 + U_STRIDE;
        if (lane < 4) {
            const int ig = 128 * (int)rank + rowb;
            #pragma unroll
            for (int dr = 0; dr < CLUSTER_N; ++dr) {
                *(float4*)cluster.map_shared_rank(db0 + ig, dr) = vA;
                *(float4*)cluster.map_shared_rank(db1 + ig, dr) = vB;
            }
            if (lane == 0) {
                const int slot = 512 + (int)rank * 8 + warp;
                #pragma unroll
                for (int dr = 0; dr < CLUSTER_N; ++dr) {
                    *cluster.map_shared_rank(db0 + slot, dr) = pA;
                    *cluster.map_shared_rank(db1 + slot, dr) = pB;
                }
            }
        }
        __syncthreads();

        if (tid < CLUSTER_N) {
            if (t & 1) MBARRIER_ARRIVE_CLUSTER(bar1, tid);
            else       MBARRIER_ARRIVE_CLUSTER(bar0, tid);
        }
    }
}

/* ---------------- launch ---------------- */

extern "C" void kernel_launch(void* const* d_in, const int* in_sizes, int n_in,
                              void* d_out, int out_size)
{
    const float* pi = (const float*)d_in[0];
    const float* A  = (const float*)d_in[1];
    const float* E  = (const float*)d_in[2];
    const int*   x  = (const int*)d_in[3];
    const int*   T  = (const int*)d_in[4];
    float* out = (float*)d_out;

    cudaFuncSetAttribute(hmm_main, cudaFuncAttributeMaxDynamicSharedMemorySize, SMEM_TOTAL);

    prep_logpi<<<1, 256>>>(pi);
    prep_colsum<<<16, 256>>>(A);
    prep_pt<<<N_ST, 256>>>(A);
    prep_logE<<<N_ST, 256>>>(E);
    hmm_main<<<(BATCH / 2) * CLUSTER_N, THREADS, SMEM_TOTAL>>>(x, T, out);
}